// round 12
// baseline (speedup 1.0000x reference)
#include <cuda_runtime.h>
#include <cuda_fp16.h>
#include <math.h>

// ---------------- problem constants ----------------
#define BATCH   4096
#define C1      64
#define IMH     28
#define IMW     28
#define PH      12
#define POS     (PH*PH)         // 144
#define CL      (C1*POS)        // 9216
#define NFC     1024
#define K1K     400
#define KFC     100
#define CAP     512
#define CANDCAP 128

#define TF      288             // fused kernel threads (9 warps)
#define NW      (TF/32)         // 9

// dynamic smem layout
#define OFF_KEYS 0               // conv keys 36864 B; fc arrays alias after compaction
#define OFF_IMG  36864           // 3136
#define OFF_WTS  40000           // 6400
#define OFF_VAL  46400           // 2048
#define OFF_IDX  48448           // 2048
#define FUSED_DSM 50496
// fc aliases inside keys region
#define FC_H     0               // 4096
#define FC_BST   4096            // 4096
#define FC_KEYS  8192            // 4096
#define FC_FLAG  12288           // 1024
#define FC_CNDN  13312           // 512
#define FC_CNDK  13824           // 512
#define FC_USED  14336           // 128

// ---------------- scratch ----------------
__device__ __align__(16) __half g_Wh[CL * NFC];   // masked fc1_w^T fp16 [j][n], 18.9 MB

__device__ __forceinline__ unsigned int f2u(float f) {
    unsigned int u = __float_as_uint(f);
    return (u & 0x80000000u) ? ~u : (u | 0x80000000u);
}
__device__ __forceinline__ float u2f(unsigned int u) {
    unsigned int b = (u & 0x80000000u) ? (u & 0x7fffffffu) : ~u;
    return __uint_as_float(b);
}

// ================= K0: mask + transpose + fp16-convert fc1 weights ============
__global__ void k_prep(const float* __restrict__ w, const float* __restrict__ m) {
    __shared__ float tile[32][33];
    int jb = blockIdx.x * 32;
    int nb = blockIdx.y * 32;
    int tx = threadIdx.x, ty = threadIdx.y;   // (32, 8)
#pragma unroll
    for (int r = 0; r < 32; r += 8) {
        int n = nb + ty + r;
        int j = jb + tx;
        float wv = w[n * CL + j];
        float mv = m[n * CL + j];
        tile[ty + r][tx] = (mv < 0.5f) ? wv : 0.0f;
    }
    __syncthreads();
#pragma unroll
    for (int r = 0; r < 32; r += 8) {
        int j = jb + ty + r;
        int n = nb + tx;
        g_Wh[j * NFC + n] = __float2half(tile[tx][ty + r]);
    }
}

// ================= fused: conv+pool+kw1 -> fc1(fp16)+kw2(exact)+fc2+lsm =======
__global__ void __launch_bounds__(TF, 3) k_fused(
    const float* __restrict__ x,     const float* __restrict__ cw,
    const float* __restrict__ cb,    const float* __restrict__ duty,
    const float* __restrict__ fw,    const float* __restrict__ fmask,
    const float* __restrict__ fc1_b, const float* __restrict__ duty_fc,
    const float* __restrict__ w2,    const float* __restrict__ b2,
    float* __restrict__ out)
{
    extern __shared__ unsigned char dysm[];
    unsigned int* s_keys = (unsigned int*)(dysm + OFF_KEYS);
    float*        img    = (float*)(dysm + OFF_IMG);
    float*        wts    = (float*)(dysm + OFF_WTS);
    float*        s_val  = (float*)(dysm + OFF_VAL);
    int*          s_idx  = (int*)(dysm + OFF_IDX);
    // fc aliases (valid after conv keys consumed)
    float*         s_h     = (float*)(dysm + FC_H);
    float*         s_bst   = (float*)(dysm + FC_BST);
    unsigned int*  s_keysF = (unsigned int*)(dysm + FC_KEYS);
    unsigned char* s_flag  = (unsigned char*)(dysm + FC_FLAG);
    int*           s_cnd_n = (int*)(dysm + FC_CNDN);
    unsigned int*  s_cnd_k = (unsigned int*)(dysm + FC_CNDK);
    unsigned char* s_used  = (unsigned char*)(dysm + FC_USED);

    __shared__ float bias[C1];
    __shared__ float boost[C1];
    __shared__ unsigned int hist[256];
    __shared__ int s_wsum[NW];
    __shared__ unsigned int sel_prefix;
    __shared__ int sel_kr;
    __shared__ int s_total;
    __shared__ float s_Q[NW];
    __shared__ int s_ic[NW];
    __shared__ int s_ccnt;
    __shared__ float s_red[NW][10];
    __shared__ float s_logits[10];
    __shared__ float s_lse;

    const int tid  = threadIdx.x;
    const int b    = blockIdx.x;
    const int lane = tid & 31, wrp = tid >> 5;

    // ================= phase 1: conv + pool + keys =================
    const float* xb = x + b * (IMH * IMW);
    for (int i = tid; i < IMH * IMW; i += TF) img[i] = xb[i];
    for (int i = tid; i < C1 * 25;   i += TF) wts[i] = cw[i];
    if (tid < C1) {
        bias[tid]  = cb[tid];
        boost[tid] = expf(400.0f / 9216.0f - duty[tid]);
    }
    __syncthreads();

    {
        int pos = tid % POS;
        int cg  = tid / POS;
        int py = pos / PH, px = pos % PH;
        int r0 = py * 2, c0 = px * 2;
        float p[36];
#pragma unroll
        for (int u = 0; u < 6; u++)
#pragma unroll
            for (int v = 0; v < 6; v++)
                p[u * 6 + v] = img[(r0 + u) * IMW + (c0 + v)];
        int cbase = cg * 32;
        for (int cc = 0; cc < 32; cc++) {
            int c = cbase + cc;
            const float* wc = wts + c * 25;
            float s00 = 0.f, s01 = 0.f, s10 = 0.f, s11 = 0.f;
#pragma unroll
            for (int u = 0; u < 5; u++) {
#pragma unroll
                for (int v = 0; v < 5; v++) {
                    float wv = wc[u * 5 + v];
                    s00 = fmaf(p[u * 6 + v],     wv, s00);
                    s01 = fmaf(p[u * 6 + v + 1], wv, s01);
                    s10 = fmaf(p[u * 6 + 6 + v], wv, s10);
                    s11 = fmaf(p[u * 6 + 7 + v], wv, s11);
                }
            }
            float pv = fmaxf(fmaxf(s00, s01), fmaxf(s10, s11)) + bias[c];
            s_keys[c * POS + pos] = f2u(pv * boost[c]);
        }
    }
    __syncthreads();

    // ---- select-1: exact 400th largest via radix ----
    if (tid == 0) { sel_prefix = 0u; sel_kr = K1K; }
    __syncthreads();
    for (int shift = 24; shift >= 0; shift -= 8) {
        if (tid < 256) hist[tid] = 0u;
        __syncthreads();
        unsigned int pfx    = sel_prefix;
        unsigned int himask = (shift == 24) ? 0u : (0xFFFFFFFFu << (shift + 8));
        for (int i = tid; i < CL; i += TF) {
            unsigned int u = s_keys[i];
            if ((u & himask) == pfx) atomicAdd(&hist[(u >> shift) & 255], 1u);
        }
        __syncthreads();
        if (tid == 0) {
            int kk = sel_kr; unsigned int acc = 0;
            for (int bin = 255; bin >= 0; --bin) {
                unsigned int h = hist[bin];
                if (acc + h >= (unsigned)kk) {
                    sel_prefix = pfx | ((unsigned)bin << shift);
                    sel_kr = kk - (int)acc;
                    break;
                }
                acc += h;
            }
        }
        __syncthreads();
    }
    unsigned int thr1 = sel_prefix;

    // ---- deterministic compaction into smem ----
    {
        int mycnt = 0;
        for (int i = tid; i < CL; i += TF)
            if (s_keys[i] >= thr1) mycnt++;
        int v = mycnt;
#pragma unroll
        for (int d = 1; d < 32; d <<= 1) {
            int t = __shfl_up_sync(0xFFFFFFFFu, v, d);
            if (lane >= d) v += t;
        }
        if (lane == 31) s_wsum[wrp] = v;
        __syncthreads();
        if (tid == 0) {
            int a = 0;
            for (int w = 0; w < NW; w++) { int t = s_wsum[w]; s_wsum[w] = a; a += t; }
            s_total = a > CAP ? CAP : a;
        }
        __syncthreads();
        int off = s_wsum[wrp] + v - mycnt;
        for (int i = tid; i < CL; i += TF) {
            unsigned int k = s_keys[i];
            if (k >= thr1) {
                if (off < CAP) {
                    s_idx[off] = i;
                    s_val[off] = u2f(k) / boost[i / POS];
                }
                off++;
            }
        }
    }
    __syncthreads();
    const int cnt = s_total;
    // s_keys region now free -> fc aliases

    // ================= phase 2: fc1 (fp16) + exact kwinners + fc2 =============
    float myQ = 0.f;
    for (int i = tid; i < cnt; i += TF) {
        float vv = s_val[i];
        myQ = fmaf(vv, vv, myQ);
    }
#pragma unroll
    for (int d = 16; d > 0; d >>= 1) myQ += __shfl_down_sync(0xFFFFFFFFu, myQ, d);
    if (lane == 0) s_Q[wrp] = myQ;
    if (tid == 0) s_ccnt = 0;
    __syncthreads();
    float Q2 = 0.f;
#pragma unroll
    for (int w = 0; w < NW; w++) Q2 += s_Q[w];

    // fp16 sparse accumulate: threads 0..255 own 4 neurons each
    if (tid < 256) {
        float a0 = 0.f, a1 = 0.f, a2 = 0.f, a3 = 0.f;
        const uint2* __restrict__ W8 = (const uint2*)g_Wh;
#pragma unroll 8
        for (int e = 0; e < cnt; e++) {
            float vv = s_val[e];
            int   j  = s_idx[e];
            uint2 wraw = __ldg(&W8[j * (NFC / 4) + tid]);
            float2 f01 = __half22float2(*(const __half2*)&wraw.x);
            float2 f23 = __half22float2(*(const __half2*)&wraw.y);
            a0 = fmaf(vv, f01.x, a0);
            a1 = fmaf(vv, f01.y, a1);
            a2 = fmaf(vv, f23.x, a2);
            a3 = fmaf(vv, f23.y, a3);
        }
        const float kdn = 100.0f / 1024.0f;
        int n = tid * 4;
        float h0 = a0 + fc1_b[n],     h1 = a1 + fc1_b[n + 1];
        float h2 = a2 + fc1_b[n + 2], h3 = a3 + fc1_b[n + 3];
        float b0 = expf(kdn - duty_fc[n]),      b1 = expf(kdn - duty_fc[n + 1]);
        float b2v = expf(kdn - duty_fc[n + 2]), b3 = expf(kdn - duty_fc[n + 3]);
        s_h[n] = h0; s_h[n+1] = h1; s_h[n+2] = h2; s_h[n+3] = h3;
        s_bst[n] = b0; s_bst[n+1] = b1; s_bst[n+2] = b2v; s_bst[n+3] = b3;
        s_keysF[n]   = f2u(h0 * b0);
        s_keysF[n+1] = f2u(h1 * b1);
        s_keysF[n+2] = f2u(h2 * b2v);
        s_keysF[n+3] = f2u(h3 * b3);
    }
    __syncthreads();

    // ---- select-2: approx rank-100 threshold ----
    if (tid == 0) { sel_prefix = 0u; sel_kr = KFC; }
    __syncthreads();
    for (int shift = 24; shift >= 0; shift -= 8) {
        if (tid < 256) hist[tid] = 0u;
        __syncthreads();
        unsigned int pfx    = sel_prefix;
        unsigned int himask = (shift == 24) ? 0u : (0xFFFFFFFFu << (shift + 8));
        if (tid < 256) {
#pragma unroll
            for (int q = 0; q < 4; q++) {
                unsigned int u = s_keysF[tid * 4 + q];
                if ((u & himask) == pfx) atomicAdd(&hist[(u >> shift) & 255], 1u);
            }
        }
        __syncthreads();
        if (tid == 0) {
            int kk = sel_kr; unsigned int acc = 0;
            for (int bin = 255; bin >= 0; --bin) {
                unsigned int h = hist[bin];
                if (acc + h >= (unsigned)kk) {
                    sel_prefix = pfx | ((unsigned)bin << shift);
                    sel_kr = kk - (int)acc;
                    break;
                }
                acc += h;
            }
        }
        __syncthreads();
    }
    const unsigned int thr = sel_prefix;
    const float tval = __uint_as_float((thr & 0x80000000u) ? (thr & 0x7fffffffu) : ~thr);
    const float mband = 4.0e-3f * sqrtf(Q2 * 6.0e-5f) + 1.0e-4f;

    // ---- flag pass ----
    if (tid < 256) {
#pragma unroll
        for (int q = 0; q < 4; q++) {
            int n = tid * 4 + q;
            float hb = s_h[n] * s_bst[n];
            unsigned char fl = (s_keysF[n] >= thr) ? 1 : 0;
            if (fabsf(hb - tval) <= mband) {
                fl = 2;
                int pos = atomicAdd(&s_ccnt, 1);
                if (pos < CANDCAP) s_cnd_n[pos] = n;
            }
            s_flag[n] = fl;
        }
    }
    __syncthreads();
    int ccnt = min(s_ccnt, CANDCAP);

    // ---- exact fp32 recompute for candidates (one warp per candidate) ----
    for (int c = wrp; c < ccnt; c += NW) {
        int n = s_cnd_n[c];
        const float* wrow = fw    + (size_t)n * CL;
        const float* mrow = fmask + (size_t)n * CL;
        float part = 0.f;
        for (int ee = lane; ee < cnt; ee += 32) {
            int j = s_idx[ee];
            float wv = __ldg(&wrow[j]);
            float mv = __ldg(&mrow[j]);
            if (mv < 0.5f) part = fmaf(s_val[ee], wv, part);
        }
#pragma unroll
        for (int d = 16; d > 0; d >>= 1)
            part += __shfl_down_sync(0xFFFFFFFFu, part, d);
        if (lane == 0) {
            float h = part + fc1_b[n];
            s_h[n] = h;
            s_cnd_k[c] = f2u(h * s_bst[n]);
        }
    }
    __syncthreads();

    // ---- resolve candidates exactly ----
    {
        int myc = 0;
        if (tid < 256) {
#pragma unroll
            for (int q = 0; q < 4; q++) myc += (s_flag[tid * 4 + q] == 1);
        }
#pragma unroll
        for (int d = 16; d > 0; d >>= 1) myc += __shfl_down_sync(0xFFFFFFFFu, myc, d);
        if (lane == 0) s_ic[wrp] = myc;
    }
    __syncthreads();
    if (tid == 0) {
        int ic = 0;
#pragma unroll
        for (int w = 0; w < NW; w++) ic += s_ic[w];
        int r = KFC - ic;
        if (r < 1) r = 1;
        if (r > ccnt) r = ccnt;
        for (int c = 0; c < ccnt; c++) s_used[c] = 0;
        unsigned int kth = 0u;
        for (int s = 0; s < r; s++) {
            int bi = -1; unsigned int bk = 0u;
            for (int c = 0; c < ccnt; c++)
                if (!s_used[c] && (bi < 0 || s_cnd_k[c] > bk)) { bi = c; bk = s_cnd_k[c]; }
            s_used[bi] = 1; kth = bk;
        }
        for (int c = 0; c < ccnt; c++)
            s_flag[s_cnd_n[c]] = (s_cnd_k[c] >= kth) ? 1 : 0;
    }
    __syncthreads();

    // ---- fc2 over winners ----
    float part[10];
#pragma unroll
    for (int c = 0; c < 10; c++) part[c] = 0.f;
    if (tid < 256) {
#pragma unroll
        for (int q = 0; q < 4; q++) {
            int n = tid * 4 + q;
            unsigned char fl = s_flag[n];
            bool win = (fl == 1) || (fl == 2 && s_keysF[n] >= thr);
            if (win) {
                float hv = s_h[n];
#pragma unroll
                for (int c = 0; c < 10; c++)
                    part[c] = fmaf(hv, w2[c * NFC + n], part[c]);
            }
        }
    }
#pragma unroll
    for (int c = 0; c < 10; c++) {
        float pv = part[c];
#pragma unroll
        for (int d = 16; d > 0; d >>= 1)
            pv += __shfl_down_sync(0xFFFFFFFFu, pv, d);
        if (lane == 0) s_red[wrp][c] = pv;
    }
    __syncthreads();
    if (tid < 10) {
        float s = 0.f;
#pragma unroll
        for (int w = 0; w < NW; w++) s += s_red[w][tid];
        s_logits[tid] = s + b2[tid];
    }
    __syncthreads();
    if (tid == 0) {
        float mx = s_logits[0];
        for (int c = 1; c < 10; c++) mx = fmaxf(mx, s_logits[c]);
        float se = 0.f;
        for (int c = 0; c < 10; c++) se += expf(s_logits[c] - mx);
        s_lse = mx + logf(se);
    }
    __syncthreads();
    if (tid < 10) out[b * 10 + tid] = s_logits[tid] - s_lse;
}

// ================= launch =================
extern "C" void kernel_launch(void* const* d_in, const int* in_sizes, int n_in,
                              void* d_out, int out_size)
{
    const float* x        = (const float*)d_in[0];
    const float* c1_w     = (const float*)d_in[1];
    const float* c1_b     = (const float*)d_in[2];
    const float* duty_cnn = (const float*)d_in[3];
    const float* fc1_w    = (const float*)d_in[4];
    const float* fc1_mask = (const float*)d_in[5];
    const float* fc1_b    = (const float*)d_in[6];
    const float* duty_fc  = (const float*)d_in[7];
    const float* fc2_w    = (const float*)d_in[8];
    const float* fc2_b    = (const float*)d_in[9];
    float* out = (float*)d_out;

    cudaFuncSetAttribute(k_fused, cudaFuncAttributeMaxDynamicSharedMemorySize,
                         FUSED_DSM);

    k_prep<<<dim3(CL / 32, NFC / 32), dim3(32, 8)>>>(fc1_w, fc1_mask);
    k_fused<<<BATCH, TF, FUSED_DSM>>>(x, c1_w, c1_b, duty_cnn,
                                      fc1_w, fc1_mask, fc1_b, duty_fc,
                                      fc2_w, fc2_b, out);
}

// round 13
// speedup vs baseline: 1.2903x; 1.2903x over previous
#include <cuda_runtime.h>
#include <cuda_fp16.h>
#include <math.h>

// ---------------- problem constants ----------------
#define BATCH   4096
#define C1      64
#define IMH     28
#define IMW     28
#define PH      12
#define POS     (PH*PH)         // 144
#define CL      (C1*POS)        // 9216
#define NFC     1024
#define K1K     400
#define KFC     100
#define CAP     512
#define CANDCAP 128

// ---------------- scratch (static device globals) ----------------
__device__ __align__(16) __half g_Wh[CL * NFC];   // masked fc1_w^T fp16 [j][n], 18.9 MB
__device__ __align__(16) float2 g_pair[BATCH * CAP];  // {val, as_float(j*256)}
__device__ int            g_cnt[BATCH];

// order-preserving float <-> uint transforms
__device__ __forceinline__ unsigned int f2u(float f) {
    unsigned int u = __float_as_uint(f);
    return (u & 0x80000000u) ? ~u : (u | 0x80000000u);
}
__device__ __forceinline__ float u2f(unsigned int u) {
    unsigned int b = (u & 0x80000000u) ? (u & 0x7fffffffu) : ~u;
    return __uint_as_float(b);
}

// warp-parallel exact bin selection over hist[256], descending bins.
// Executed by one full warp. Exactly one lane finds the bin; it updates
// sel_prefix/sel_kr in smem. Semantics identical to the serial scan.
__device__ __forceinline__ void warp_select_bin(
    const unsigned int* hist, int kk, int lane, int shift, unsigned int pfx,
    volatile unsigned int* sel_prefix, volatile int* sel_kr)
{
    int base = 255 - lane * 8;
    unsigned int hb[8];
    unsigned int s = 0;
#pragma unroll
    for (int q = 0; q < 8; q++) { hb[q] = hist[base - q]; s += hb[q]; }
    unsigned int incl = s;
#pragma unroll
    for (int d = 1; d < 32; d <<= 1) {
        unsigned int t = __shfl_up_sync(0xFFFFFFFFu, incl, d);
        if (lane >= d) incl += t;
    }
    unsigned int excl = incl - s;
    if (excl < (unsigned)kk && (unsigned)kk <= incl) {
        unsigned int acc = excl;
#pragma unroll
        for (int q = 0; q < 8; q++) {
            if (acc + hb[q] >= (unsigned)kk) {
                *sel_prefix = pfx | ((unsigned)(base - q) << shift);
                *sel_kr = kk - (int)acc;
                break;
            }
            acc += hb[q];
        }
    }
}

// ================= K0: mask + transpose + fp16-convert fc1 weights ============
__global__ void k_prep(const float* __restrict__ w, const float* __restrict__ m) {
    __shared__ float tile[32][33];
    int jb = blockIdx.x * 32;
    int nb = blockIdx.y * 32;
    int tx = threadIdx.x, ty = threadIdx.y;   // (32, 8)
#pragma unroll
    for (int r = 0; r < 32; r += 8) {
        int n = nb + ty + r;
        int j = jb + tx;
        float wv = w[n * CL + j];
        float mv = m[n * CL + j];
        tile[ty + r][tx] = (mv < 0.5f) ? wv : 0.0f;
    }
    __syncthreads();
#pragma unroll
    for (int r = 0; r < 32; r += 8) {
        int j = jb + ty + r;
        int n = nb + tx;
        g_Wh[j * NFC + n] = __float2half(tile[tx][ty + r]);
    }
}

// ================= K1: fused conv + pool + kwinners(400/9216) =================
#define T1 288

__global__ void __launch_bounds__(T1) k_conv_pool_kw(
    const float* __restrict__ x, const float* __restrict__ cw,
    const float* __restrict__ cb, const float* __restrict__ duty)
{
    __shared__ unsigned int s_keys[CL];    // 36 KB
    __shared__ float img[IMH * IMW];
    __shared__ float wts[C1 * 25];
    __shared__ float bias[C1];
    __shared__ float boost[C1];
    __shared__ unsigned int hist[256];
    __shared__ int s_wsum[16];
    __shared__ unsigned int sel_prefix;
    __shared__ int sel_kr;
    __shared__ int sel_total;

    const int tid = threadIdx.x;
    const int b   = blockIdx.x;
    const int lane = tid & 31, wrp = tid >> 5;

    const float* xb = x + b * (IMH * IMW);
    for (int i = tid; i < IMH * IMW; i += T1) img[i] = xb[i];
    for (int i = tid; i < C1 * 25;   i += T1) wts[i] = cw[i];
    if (tid < C1) {
        bias[tid]  = cb[tid];
        boost[tid] = expf(400.0f / 9216.0f - duty[tid]);
    }
    __syncthreads();

    // ---- conv 5x5 + maxpool 2x2, scalar fp32, patch in registers ----
    {
        int pos = tid % POS;
        int cg  = tid / POS;
        int py = pos / PH, px = pos % PH;
        int r0 = py * 2, c0 = px * 2;
        float p[36];
#pragma unroll
        for (int u = 0; u < 6; u++)
#pragma unroll
            for (int v = 0; v < 6; v++)
                p[u * 6 + v] = img[(r0 + u) * IMW + (c0 + v)];
        int cbase = cg * 32;
        for (int cc = 0; cc < 32; cc++) {
            int c = cbase + cc;
            const float* wc = wts + c * 25;
            float s00 = 0.f, s01 = 0.f, s10 = 0.f, s11 = 0.f;
#pragma unroll
            for (int u = 0; u < 5; u++) {
#pragma unroll
                for (int v = 0; v < 5; v++) {
                    float wv = wc[u * 5 + v];
                    s00 = fmaf(p[u * 6 + v],     wv, s00);
                    s01 = fmaf(p[u * 6 + v + 1], wv, s01);
                    s10 = fmaf(p[u * 6 + 6 + v], wv, s10);
                    s11 = fmaf(p[u * 6 + 7 + v], wv, s11);
                }
            }
            float pv = fmaxf(fmaxf(s00, s01), fmaxf(s10, s11)) + bias[c];
            s_keys[c * POS + pos] = f2u(pv * boost[c]);
        }
    }
    __syncthreads();

    // ---- exact k-th largest via 4-pass radix select (warp-parallel bins) ----
    if (tid == 0) { sel_prefix = 0u; sel_kr = K1K; }
    __syncthreads();
    for (int shift = 24; shift >= 0; shift -= 8) {
        if (tid < 256) hist[tid] = 0u;
        __syncthreads();
        unsigned int pfx    = sel_prefix;
        int          kk     = sel_kr;
        unsigned int himask = (shift == 24) ? 0u : (0xFFFFFFFFu << (shift + 8));
        for (int i = tid; i < CL; i += T1) {
            unsigned int u = s_keys[i];
            if ((u & himask) == pfx) atomicAdd(&hist[(u >> shift) & 255], 1u);
        }
        __syncthreads();
        if (wrp == 0)
            warp_select_bin(hist, kk, lane, shift, pfx, &sel_prefix, &sel_kr);
        __syncthreads();
    }
    unsigned int thr = sel_prefix;

    // ---- deterministic compaction (fused pair write) ----
    int mycnt = 0;
    for (int i = tid; i < CL; i += T1)
        if (s_keys[i] >= thr) mycnt++;

    int v = mycnt;
#pragma unroll
    for (int d = 1; d < 32; d <<= 1) {
        int t = __shfl_up_sync(0xFFFFFFFFu, v, d);
        if (lane >= d) v += t;
    }
    if (lane == 31) s_wsum[wrp] = v;
    __syncthreads();
    if (tid == 0) {
        int a = 0;
        for (int w = 0; w < T1 / 32; w++) { int t = s_wsum[w]; s_wsum[w] = a; a += t; }
        sel_total = a;
    }
    __syncthreads();
    int off = s_wsum[wrp] + v - mycnt;
    for (int i = tid; i < CL; i += T1) {
        unsigned int k = s_keys[i];
        if (k >= thr) {
            if (off < CAP) {
                g_pair[b * CAP + off] =
                    make_float2(u2f(k) / boost[i / POS],
                                __int_as_float(i << 8));   // j * (NFC/4)
            }
            off++;
        }
    }
    if (tid == 0) g_cnt[b] = sel_total > CAP ? CAP : sel_total;
}

// ================= K2: fp16 fc1 + exact-boundary kwinners + fc2 + lsm =========
#define T2 256

__global__ void __launch_bounds__(T2) k_fc_out(
    const float* __restrict__ fw,    const float* __restrict__ fmask,
    const float* __restrict__ fc1_b, const float* __restrict__ duty_fc,
    const float* __restrict__ w2,    const float* __restrict__ b2,
    float* __restrict__ out)
{
    __shared__ float2        s_pair[CAP];
    __shared__ float         s_h[NFC];
    __shared__ float         s_bst[NFC];
    __shared__ unsigned int  s_keys[NFC];
    __shared__ unsigned char s_flag[NFC];
    __shared__ unsigned int  hist[256];
    __shared__ unsigned int  sel_prefix;
    __shared__ int           sel_kr;
    __shared__ float         s_red[8][10];
    __shared__ float         s_logits[10];
    __shared__ float         s_lse;
    __shared__ float         s_Q[8];
    __shared__ int           s_ic[8];
    __shared__ int           s_ccnt;
    __shared__ int           s_cnd_n[CANDCAP];
    __shared__ unsigned int  s_cnd_k[CANDCAP];
    __shared__ unsigned char s_used[CANDCAP];

    const int tid  = threadIdx.x;
    const int b    = blockIdx.x;
    const int lane = tid & 31, wrp = tid >> 5;

    int cnt = g_cnt[b];
    float myQ = 0.f;
    for (int i = tid; i < cnt; i += T2) {
        float2 pr = g_pair[b * CAP + i];
        s_pair[i] = pr;
        myQ = fmaf(pr.x, pr.x, myQ);
    }
#pragma unroll
    for (int d = 16; d > 0; d >>= 1) myQ += __shfl_down_sync(0xFFFFFFFFu, myQ, d);
    if (lane == 0) s_Q[wrp] = myQ;
    if (tid == 0) s_ccnt = 0;
    __syncthreads();
    float Q2 = 0.f;
#pragma unroll
    for (int w = 0; w < 8; w++) Q2 += s_Q[w];

    // ---- fp16 sparse accumulate: fused pair LDS.64 + pre-scaled index ----
    float a0 = 0.f, a1 = 0.f, a2 = 0.f, a3 = 0.f;
    const uint2* __restrict__ W8 = (const uint2*)g_Wh;  // 8B = 4 halfs
#pragma unroll 8
    for (int e = 0; e < cnt; e++) {
        float2 pv = s_pair[e];
        int jn = __float_as_int(pv.y);           // j * 256
        uint2 wraw = __ldg(&W8[jn + tid]);
        float2 f01 = __half22float2(*(const __half2*)&wraw.x);
        float2 f23 = __half22float2(*(const __half2*)&wraw.y);
        a0 = fmaf(pv.x, f01.x, a0);
        a1 = fmaf(pv.x, f01.y, a1);
        a2 = fmaf(pv.x, f23.x, a2);
        a3 = fmaf(pv.x, f23.y, a3);
    }

    const float kdn = 100.0f / 1024.0f;
    {
        int n = tid * 4;
        float h0 = a0 + fc1_b[n],     h1 = a1 + fc1_b[n + 1];
        float h2 = a2 + fc1_b[n + 2], h3 = a3 + fc1_b[n + 3];
        float b0 = expf(kdn - duty_fc[n]),      b1 = expf(kdn - duty_fc[n + 1]);
        float b2v = expf(kdn - duty_fc[n + 2]), b3 = expf(kdn - duty_fc[n + 3]);
        s_h[n] = h0; s_h[n+1] = h1; s_h[n+2] = h2; s_h[n+3] = h3;
        s_bst[n] = b0; s_bst[n+1] = b1; s_bst[n+2] = b2v; s_bst[n+3] = b3;
        s_keys[n]   = f2u(h0 * b0);
        s_keys[n+1] = f2u(h1 * b1);
        s_keys[n+2] = f2u(h2 * b2v);
        s_keys[n+3] = f2u(h3 * b3);
    }
    __syncthreads();

    // ---- radix select approx rank-100 threshold (warp-parallel bins) ----
    if (tid == 0) { sel_prefix = 0u; sel_kr = KFC; }
    __syncthreads();
    for (int shift = 24; shift >= 0; shift -= 8) {
        hist[tid] = 0u;
        __syncthreads();
        unsigned int pfx    = sel_prefix;
        int          kk     = sel_kr;
        unsigned int himask = (shift == 24) ? 0u : (0xFFFFFFFFu << (shift + 8));
#pragma unroll
        for (int q = 0; q < 4; q++) {
            unsigned int u = s_keys[tid * 4 + q];
            if ((u & himask) == pfx) atomicAdd(&hist[(u >> shift) & 255], 1u);
        }
        __syncthreads();
        if (wrp == 0)
            warp_select_bin(hist, kk, lane, shift, pfx, &sel_prefix, &sel_kr);
        __syncthreads();
    }
    const unsigned int thr = sel_prefix;
    const float tval = __uint_as_float((thr & 0x80000000u) ? (thr & 0x7fffffffu) : ~thr);
    const float mband = 4.0e-3f * sqrtf(Q2 * 6.0e-5f) + 1.0e-4f;

    // ---- flag pass ----
#pragma unroll
    for (int q = 0; q < 4; q++) {
        int n = tid * 4 + q;
        float hb = s_h[n] * s_bst[n];
        unsigned char fl = (s_keys[n] >= thr) ? 1 : 0;
        if (fabsf(hb - tval) <= mband) {
            fl = 2;
            int pos = atomicAdd(&s_ccnt, 1);
            if (pos < CANDCAP) s_cnd_n[pos] = n;
        }
        s_flag[n] = fl;
    }
    __syncthreads();
    int ccnt = min(s_ccnt, CANDCAP);

    // ---- exact fp32 recompute for candidates from ORIGINAL weights+mask ----
    for (int c = wrp; c < ccnt; c += 8) {
        int n = s_cnd_n[c];
        const float* wrow = fw    + (size_t)n * CL;
        const float* mrow = fmask + (size_t)n * CL;
        float part = 0.f;
        for (int ee = lane; ee < cnt; ee += 32) {
            float2 pr = s_pair[ee];
            int j = __float_as_int(pr.y) >> 8;
            float wv = __ldg(&wrow[j]);
            float mv = __ldg(&mrow[j]);
            if (mv < 0.5f) part = fmaf(pr.x, wv, part);
        }
#pragma unroll
        for (int d = 16; d > 0; d >>= 1)
            part += __shfl_down_sync(0xFFFFFFFFu, part, d);
        if (lane == 0) {
            float h = part + fc1_b[n];
            s_h[n] = h;
            s_cnd_k[c] = f2u(h * s_bst[n]);
        }
    }
    __syncthreads();

    // ---- count definite-ins, resolve candidates exactly ----
    {
        int myc = 0;
#pragma unroll
        for (int q = 0; q < 4; q++) myc += (s_flag[tid * 4 + q] == 1);
#pragma unroll
        for (int d = 16; d > 0; d >>= 1) myc += __shfl_down_sync(0xFFFFFFFFu, myc, d);
        if (lane == 0) s_ic[wrp] = myc;
    }
    __syncthreads();
    if (tid == 0) {
        int ic = 0;
#pragma unroll
        for (int w = 0; w < 8; w++) ic += s_ic[w];
        int r = KFC - ic;
        if (r < 1) r = 1;
        if (r > ccnt) r = ccnt;
        for (int c = 0; c < ccnt; c++) s_used[c] = 0;
        unsigned int kth = 0u;
        for (int s = 0; s < r; s++) {
            int bi = -1; unsigned int bk = 0u;
            for (int c = 0; c < ccnt; c++)
                if (!s_used[c] && (bi < 0 || s_cnd_k[c] > bk)) { bi = c; bk = s_cnd_k[c]; }
            s_used[bi] = 1; kth = bk;
        }
        for (int c = 0; c < ccnt; c++)
            s_flag[s_cnd_n[c]] = (s_cnd_k[c] >= kth) ? 1 : 0;
    }
    __syncthreads();

    // ---- fc2 over winners ----
    float part[10];
#pragma unroll
    for (int c = 0; c < 10; c++) part[c] = 0.f;
#pragma unroll
    for (int q = 0; q < 4; q++) {
        int n = tid * 4 + q;
        unsigned char fl = s_flag[n];
        bool win = (fl == 1) || (fl == 2 && s_keys[n] >= thr);
        if (win) {
            float hv = s_h[n];
#pragma unroll
            for (int c = 0; c < 10; c++)
                part[c] = fmaf(hv, w2[c * NFC + n], part[c]);
        }
    }
#pragma unroll
    for (int c = 0; c < 10; c++) {
        float pv = part[c];
#pragma unroll
        for (int d = 16; d > 0; d >>= 1)
            pv += __shfl_down_sync(0xFFFFFFFFu, pv, d);
        if (lane == 0) s_red[wrp][c] = pv;
    }
    __syncthreads();
    if (tid < 10) {
        float s = 0.f;
#pragma unroll
        for (int w = 0; w < 8; w++) s += s_red[w][tid];
        s_logits[tid] = s + b2[tid];
    }
    __syncthreads();
    if (tid == 0) {
        float mx = s_logits[0];
        for (int c = 1; c < 10; c++) mx = fmaxf(mx, s_logits[c]);
        float se = 0.f;
        for (int c = 0; c < 10; c++) se += expf(s_logits[c] - mx);
        s_lse = mx + logf(se);
    }
    __syncthreads();
    if (tid < 10) out[b * 10 + tid] = s_logits[tid] - s_lse;
}

// ================= launch =================
extern "C" void kernel_launch(void* const* d_in, const int* in_sizes, int n_in,
                              void* d_out, int out_size)
{
    const float* x        = (const float*)d_in[0];
    const float* c1_w     = (const float*)d_in[1];
    const float* c1_b     = (const float*)d_in[2];
    const float* duty_cnn = (const float*)d_in[3];
    const float* fc1_w    = (const float*)d_in[4];
    const float* fc1_mask = (const float*)d_in[5];
    const float* fc1_b    = (const float*)d_in[6];
    const float* duty_fc  = (const float*)d_in[7];
    const float* fc2_w    = (const float*)d_in[8];
    const float* fc2_b    = (const float*)d_in[9];
    float* out = (float*)d_out;

    k_prep<<<dim3(CL / 32, NFC / 32), dim3(32, 8)>>>(fc1_w, fc1_mask);
    k_conv_pool_kw<<<BATCH, T1>>>(x, c1_w, c1_b, duty_cnn);
    k_fc_out<<<BATCH, T2>>>(fc1_w, fc1_mask, fc1_b, duty_fc, fc2_w, fc2_b, out);
}